// round 1
// baseline (speedup 1.0000x reference)
#include <cuda_runtime.h>
#include <cstdint>

#define Bb 4
#define Cc 64
#define Hh 256
#define Ww 320
#define HW (Hh*Ww)
#define BHW (Bb*HW)
#define NOC 83          // 8 (w3) + 24 (w5) + 48 (w7) + 3 (ck)
#define NWK 83          // 9 + 25 + 49 propagation weight channels
#define EPSW 1e-6f
#define BN_EPS 1e-5f

// ---------------- device scratch (allocation-free rule: __device__ globals) ----
__device__ float g_wflat[64 * (NOC*9)];          // weights reordered: [c][oc][k]
__device__ float g_convout[(size_t)NOC * BHW];   // conv output, channel-major
__device__ float g_stats[2 * NOC];               // sums, sumsqs
__device__ float g_scale[NOC];
__device__ float g_shift[NOC];
__device__ float g_weights[(size_t)NWK * BHW];   // k-major: [0..8]=w3,[9..33]=w5,[34..82]=w7
__device__ float g_conf[3 * BHW];
__device__ float g_hnA[3 * BHW];
__device__ float g_hnB[3 * BHW];
__device__ float g_hns[3 * BHW];                 // [hn, mix@3, mix@6]

// ---------------- K0: reorder conv weights to [c][oc][9], zero stats ----------
__global__ void reorg_kernel(const float* __restrict__ w3, const float* __restrict__ w5,
                             const float* __restrict__ w7, const float* __restrict__ ck) {
    int i = blockIdx.x * blockDim.x + threadIdx.x;
    if (i < 2 * NOC) g_stats[i] = 0.f;
    if (i >= 64 * NOC * 9) return;
    int k  = i % 9;
    int t  = i / 9;
    int oc = t % NOC;
    int c  = t / NOC;
    float v;
    if (oc < 8)        v = w3[(oc      * 64 + c) * 9 + k];
    else if (oc < 32)  v = w5[((oc-8)  * 64 + c) * 9 + k];
    else if (oc < 80)  v = w7[((oc-32) * 64 + c) * 9 + k];
    else               v = ck[((oc-80) * 64 + c) * 9 + k];
    g_wflat[c * (NOC*9) + oc * 9 + k] = v;
}

// ---------------- K1: 83-channel 3x3 SAME conv (no bias) ----------------------
#define TX 16
#define TY 8
__global__ __launch_bounds__(128) void conv83_kernel(const float* __restrict__ fout) {
    __shared__ __align__(16) float wsm[NOC * 12];   // 9 padded to 12 for float4
    __shared__ float tile[(TY+2)*(TX+2)];           // 10 x 18

    int tid = threadIdx.x;
    int tx = tid & (TX-1);
    int ty = tid >> 4;
    int bidx = blockIdx.x;
    const int bw = Ww / TX;   // 20
    const int bh = Hh / TY;   // 32
    int bx = bidx % bw;
    int t2 = bidx / bw;
    int by = t2 % bh;
    int b  = t2 / bh;
    int x0 = bx * TX, y0 = by * TY;

    float acc[NOC];
#pragma unroll
    for (int i = 0; i < NOC; i++) acc[i] = 0.f;

    for (int c = 0; c < Cc; c++) {
        const float* src = fout + ((size_t)(b * Cc + c)) * HW;
        // load input tile (with halo, zero-pad)
        for (int i = tid; i < (TY+2)*(TX+2); i += 128) {
            int yy = i / (TX+2), xx = i % (TX+2);
            int gy = y0 + yy - 1, gx = x0 + xx - 1;
            float v = 0.f;
            if (gy >= 0 && gy < Hh && gx >= 0 && gx < Ww) v = src[gy * Ww + gx];
            tile[i] = v;
        }
        // load weights for this input channel
        const float* wsrc = g_wflat + c * (NOC*9);
        for (int i = tid; i < NOC*9; i += 128) {
            int oc = i / 9, k = i - oc * 9;
            wsm[oc * 12 + k] = wsrc[i];
        }
        __syncthreads();

        float x0v = tile[(ty+0)*(TX+2) + tx+0];
        float x1v = tile[(ty+0)*(TX+2) + tx+1];
        float x2v = tile[(ty+0)*(TX+2) + tx+2];
        float x3v = tile[(ty+1)*(TX+2) + tx+0];
        float x4v = tile[(ty+1)*(TX+2) + tx+1];
        float x5v = tile[(ty+1)*(TX+2) + tx+2];
        float x6v = tile[(ty+2)*(TX+2) + tx+0];
        float x7v = tile[(ty+2)*(TX+2) + tx+1];
        float x8v = tile[(ty+2)*(TX+2) + tx+2];

#pragma unroll
        for (int oc = 0; oc < NOC; oc++) {
            float4 wa = *(const float4*)&wsm[oc * 12];
            float4 wb = *(const float4*)&wsm[oc * 12 + 4];
            float  w8 = wsm[oc * 12 + 8];
            float a = acc[oc];
            a = fmaf(wa.x, x0v, a); a = fmaf(wa.y, x1v, a); a = fmaf(wa.z, x2v, a);
            a = fmaf(wa.w, x3v, a); a = fmaf(wb.x, x4v, a); a = fmaf(wb.y, x5v, a);
            a = fmaf(wb.z, x6v, a); a = fmaf(wb.w, x7v, a); a = fmaf(w8,  x8v, a);
            acc[oc] = a;
        }
        __syncthreads();
    }

    int p = (b * Hh + y0 + ty) * Ww + x0 + tx;
#pragma unroll
    for (int oc = 0; oc < NOC; oc++) g_convout[(size_t)oc * BHW + p] = acc[oc];
}

// ---------------- K2a: per-channel sum / sumsq ---------------------------------
__global__ void stats_kernel() {
    int oc = blockIdx.x;                 // 0..79
    const int CHUNK = BHW / 64;          // 5120
    const float* src = g_convout + (size_t)oc * BHW + blockIdx.y * CHUNK;
    float s = 0.f, s2 = 0.f;
    for (int i = threadIdx.x; i < CHUNK; i += 256) {
        float v = src[i];
        s += v;
        s2 = fmaf(v, v, s2);
    }
#pragma unroll
    for (int o = 16; o; o >>= 1) {
        s  += __shfl_down_sync(0xffffffffu, s,  o);
        s2 += __shfl_down_sync(0xffffffffu, s2, o);
    }
    __shared__ float sh[16];
    int w = threadIdx.x >> 5, l = threadIdx.x & 31;
    if (l == 0) { sh[w] = s; sh[8 + w] = s2; }
    __syncthreads();
    if (threadIdx.x == 0) {
        float a = 0.f, b2 = 0.f;
        for (int i = 0; i < 8; i++) { a += sh[i]; b2 += sh[8 + i]; }
        atomicAdd(&g_stats[oc], a);
        atomicAdd(&g_stats[NOC + oc], b2);
    }
}

// ---------------- K2b: finalize BN affine --------------------------------------
__global__ void finalize_kernel(const float* __restrict__ w3g, const float* __restrict__ w3b,
                                const float* __restrict__ w5g, const float* __restrict__ w5b,
                                const float* __restrict__ w7g, const float* __restrict__ w7b,
                                const float* __restrict__ ckb) {
    int oc = threadIdx.x;
    if (oc >= NOC) return;
    if (oc < 80) {
        float N = (float)BHW;
        float mean = g_stats[oc] / N;
        float var  = g_stats[NOC + oc] / N - mean * mean;
        float inv  = rsqrtf(var + BN_EPS);
        float g, bb;
        if (oc < 8)       { g = w3g[oc];      bb = w3b[oc]; }
        else if (oc < 32) { g = w5g[oc - 8];  bb = w5b[oc - 8]; }
        else              { g = w7g[oc - 32]; bb = w7b[oc - 32]; }
        g_scale[oc] = g * inv;
        g_shift[oc] = bb - mean * g * inv;
    } else {
        g_scale[oc] = 1.f;
        g_shift[oc] = ckb[oc - 80];   // ck bias folded here
    }
}

// ---------------- K3: per-pixel kernel generation + conf + hn init -------------
template <int NC, int PK>
__device__ __forceinline__ void gen_group(int p, int ocbase, int kbase, float sig) {
    const int KK = PK * PK;
    float w[NC];
    float s = 0.f;
#pragma unroll
    for (int j = 0; j < NC; j++) {
        float x = g_convout[(size_t)(ocbase + j) * BHW + p];
        float v = fmaxf(fmaf(g_scale[ocbase + j], x, g_shift[ocbase + j]), 0.f);
        w[j] = v;
        s += v;
    }
    float inv = 1.f / (s + EPSW);
    float mid = 1.f - s * inv;
    const int h = (KK - 1) / 2;   // == NC/2
    float full[KK];
#pragma unroll
    for (int j = 0; j < h; j++) full[j] = w[j] * inv;
    full[h] = mid;
#pragma unroll
    for (int j = 0; j < NC - h; j++) full[h + 1 + j] = w[h + j] * inv;

    float is2 = 1.f / (2.f * sig * sig);
    float t = 0.f;
#pragma unroll
    for (int k = 0; k < KK; k++) {
        const int ki = k / PK, kj = k % PK;
        float ri = -1.f + 2.f * (float)ki / (float)(PK - 1);
        float rj = -1.f + 2.f * (float)kj / (float)(PK - 1);
        float sk = __expf(-(ri * ri + rj * rj) * is2);
        full[k] *= sk;
        t += full[k];
    }
    t = fmaxf(t, 1e-7f);
    float it = 1.f / t;
#pragma unroll
    for (int k = 0; k < KK; k++) g_weights[(size_t)(kbase + k) * BHW + p] = full[k] * it;
}

__global__ void gen_weights_kernel(const float* __restrict__ hn,
                                   const float* __restrict__ ps3,
                                   const float* __restrict__ ps5,
                                   const float* __restrict__ ps7) {
    int p = blockIdx.x * blockDim.x + threadIdx.x;
    if (p >= BHW) return;
    gen_group<8, 3>(p, 0, 0, *ps3);
    gen_group<24, 5>(p, 8, 9, *ps5);
    gen_group<48, 7>(p, 32, 34, *ps7);

    // conf = softmax over the 3 ck channels (bias already in g_shift)
    float l0 = g_convout[(size_t)80 * BHW + p] + g_shift[80];
    float l1 = g_convout[(size_t)81 * BHW + p] + g_shift[81];
    float l2 = g_convout[(size_t)82 * BHW + p] + g_shift[82];
    float m = fmaxf(l0, fmaxf(l1, l2));
    float e0 = __expf(l0 - m), e1 = __expf(l1 - m), e2 = __expf(l2 - m);
    float is = 1.f / (e0 + e1 + e2);
    g_conf[p] = e0 * is;
    g_conf[BHW + p] = e1 * is;
    g_conf[2 * BHW + p] = e2 * is;

    float hv = hn[p];
    g_hnA[p] = hv; g_hnA[BHW + p] = hv; g_hnA[2 * BHW + p] = hv;
    g_hns[p] = hv;
}

// ---------------- K4: one propagation step (all three kernels) -----------------
template <int PK>
__device__ __forceinline__ float local_conv_px(const float* __restrict__ cur,
                                               int b, int y, int x, int p, int kbase) {
    const int PAD = PK / 2;
    float acc = 0.f;
    const float* plane = cur + (size_t)b * HW;
#pragma unroll
    for (int ky = 0; ky < PK; ky++) {
        int yy = y + ky - PAD;
        bool yok = (yy >= 0) & (yy < Hh);
#pragma unroll
        for (int kx = 0; kx < PK; kx++) {
            int xx = x + kx - PAD;
            float v = 0.f;
            if (yok && xx >= 0 && xx < Ww) v = __ldg(&plane[yy * Ww + xx]);
            acc = fmaf(g_weights[(size_t)(kbase + ky * PK + kx) * BHW + p], v, acc);
        }
    }
    return acc;
}

__global__ void prop_kernel(int srcA, int mixidx) {
    int p = blockIdx.x * blockDim.x + threadIdx.x;
    if (p >= BHW) return;
    const float* cur = srcA ? g_hnA : g_hnB;
    float* nxt = srcA ? g_hnB : g_hnA;
    int b = p / HW;
    int r = p - b * HW;
    int y = r / Ww;
    int x = r - y * Ww;

    float n3 = local_conv_px<3>(cur,            b, y, x, p, 0);
    float n5 = local_conv_px<5>(cur + BHW,      b, y, x, p, 9);
    float n7 = local_conv_px<7>(cur + 2 * BHW,  b, y, x, p, 34);

    nxt[p] = n3;
    nxt[BHW + p] = n5;
    nxt[2 * BHW + p] = n7;
    if (mixidx >= 0) {
        g_hns[(size_t)mixidx * BHW + p] =
            g_conf[p] * n3 + g_conf[BHW + p] * n5 + g_conf[2 * BHW + p] * n7;
    }
}

// ---------------- K5: final conv(67ch,3x3) -> softmax -> blend ------------------
__global__ __launch_bounds__(128) void final_kernel(const float* __restrict__ fout,
                                                    const float* __restrict__ ctw,
                                                    const float* __restrict__ ctb,
                                                    float* __restrict__ out) {
    __shared__ float wct[3 * 67 * 9];               // 1809 floats
    __shared__ float tile[(TY+2)*(TX+2)];
    int tid = threadIdx.x;
    int tx = tid & (TX-1);
    int ty = tid >> 4;
    int bidx = blockIdx.x;
    const int bw = Ww / TX;
    const int bh = Hh / TY;
    int bx = bidx % bw;
    int t2 = bidx / bw;
    int by = t2 % bh;
    int b  = t2 / bh;
    int x0 = bx * TX, y0 = by * TY;

    for (int i = tid; i < 3 * 67 * 9; i += 128) wct[i] = ctw[i];

    float acc0 = 0.f, acc1 = 0.f, acc2 = 0.f;
    for (int ic = 0; ic < 67; ic++) {
        const float* src = (ic < 64)
            ? fout + ((size_t)(b * Cc + ic)) * HW
            : g_hns + (size_t)(ic - 64) * BHW + (size_t)b * HW;
        __syncthreads();
        for (int i = tid; i < (TY+2)*(TX+2); i += 128) {
            int yy = i / (TX+2), xx = i % (TX+2);
            int gy = y0 + yy - 1, gx = x0 + xx - 1;
            float v = 0.f;
            if (gy >= 0 && gy < Hh && gx >= 0 && gx < Ww) v = src[gy * Ww + gx];
            tile[i] = v;
        }
        __syncthreads();
        float xv[9];
#pragma unroll
        for (int ky = 0; ky < 3; ky++)
#pragma unroll
            for (int kx = 0; kx < 3; kx++)
                xv[ky * 3 + kx] = tile[(ty + ky) * (TX+2) + tx + kx];
#pragma unroll
        for (int k = 0; k < 9; k++) {
            acc0 = fmaf(wct[(0 * 67 + ic) * 9 + k], xv[k], acc0);
            acc1 = fmaf(wct[(1 * 67 + ic) * 9 + k], xv[k], acc1);
            acc2 = fmaf(wct[(2 * 67 + ic) * 9 + k], xv[k], acc2);
        }
    }

    int p = (b * Hh + y0 + ty) * Ww + x0 + tx;
    float l0 = acc0 + ctb[0];
    float l1 = acc1 + ctb[1];
    float l2 = acc2 + ctb[2];
    float m = fmaxf(l0, fmaxf(l1, l2));
    float e0 = __expf(l0 - m), e1 = __expf(l1 - m), e2 = __expf(l2 - m);
    float is = 1.f / (e0 + e1 + e2);
    float h0v = g_hns[p], h1v = g_hns[BHW + p], h2v = g_hns[2 * BHW + p];
    out[p] = (e0 * h0v + e1 * h1v + e2 * h2v) * is;
}

// ---------------- launch --------------------------------------------------------
extern "C" void kernel_launch(void* const* d_in, const int* in_sizes, int n_in,
                              void* d_out, int out_size) {
    const float* fout = (const float*)d_in[0];
    const float* hn   = (const float*)d_in[1];
    // d_in[2] = h0 (unused by reference)
    const float* w3c  = (const float*)d_in[3];
    const float* w3g  = (const float*)d_in[4];
    const float* w3b  = (const float*)d_in[5];
    const float* w5c  = (const float*)d_in[6];
    const float* w5g  = (const float*)d_in[7];
    const float* w5b  = (const float*)d_in[8];
    const float* w7c  = (const float*)d_in[9];
    const float* w7g  = (const float*)d_in[10];
    const float* w7b  = (const float*)d_in[11];
    const float* ckw  = (const float*)d_in[12];
    const float* ckb  = (const float*)d_in[13];
    const float* ctw  = (const float*)d_in[14];
    const float* ctb  = (const float*)d_in[15];
    const float* s3   = (const float*)d_in[16];
    const float* s5   = (const float*)d_in[17];
    const float* s7   = (const float*)d_in[18];
    float* out = (float*)d_out;

    // K0: reorder weights + zero stats
    {
        int n = 64 * NOC * 9;
        reorg_kernel<<<(n + 255) / 256, 256>>>(w3c, w5c, w7c, ckw);
    }
    // K1: big conv
    conv83_kernel<<<(Ww/TX) * (Hh/TY) * Bb, 128>>>(fout);
    // K2: BN statistics
    {
        dim3 g(80, 64);
        stats_kernel<<<g, 256>>>();
    }
    finalize_kernel<<<1, 96>>>(w3g, w3b, w5g, w5b, w7g, w7b, ckb);
    // K3: per-pixel weight generation + conf + hn init
    gen_weights_kernel<<<BHW / 256, 256>>>(hn, s3, s5, s7);
    // K4: 6 propagation iterations (ping-pong A<->B), mixes at iter 2 and 5
    prop_kernel<<<BHW / 256, 256>>>(1, -1);   // A -> B
    prop_kernel<<<BHW / 256, 256>>>(0, -1);   // B -> A
    prop_kernel<<<BHW / 256, 256>>>(1,  1);   // A -> B, mix -> hns[1]
    prop_kernel<<<BHW / 256, 256>>>(0, -1);   // B -> A
    prop_kernel<<<BHW / 256, 256>>>(1, -1);   // A -> B
    prop_kernel<<<BHW / 256, 256>>>(0,  2);   // B -> A, mix -> hns[2]
    // K5: final conv + softmax blend
    final_kernel<<<(Ww/TX) * (Hh/TY) * Bb, 128>>>(fout, ctw, ctb, out);
}